// round 1
// baseline (speedup 1.0000x reference)
#include <cuda_runtime.h>
#include <cstdint>

// Problem constants (shapes fixed by the dataset)
#define NMAX 100000
#define EMAX 1600000

// Scratch (device globals: allocation-free rule)
__device__ int   g_deg[NMAX];
__device__ float g_dinv[NMAX];
__device__ float g_h1  [(size_t)NMAX * 128];   // dinv-scaled conv1 transform (then reused for relu output)
__device__ float g_agg1[(size_t)NMAX * 128];   // conv1 aggregation
__device__ float g_h2  [(size_t)NMAX * 64];    // dinv-scaled conv2 transform

// ---------------------------------------------------------------------------
// Degree / normalization
// ---------------------------------------------------------------------------
__global__ void k_deg_init(int n) {
    int i = blockIdx.x * blockDim.x + threadIdx.x;
    if (i < n) g_deg[i] = 1;  // self loop
}

__global__ void k_deg_count(const int* __restrict__ ei, int E) {
    int i = blockIdx.x * blockDim.x + threadIdx.x;
    if (i < E) atomicAdd(&g_deg[ei[E + i]], 1);
}

__global__ void k_dinv(int n) {
    int i = blockIdx.x * blockDim.x + threadIdx.x;
    if (i < n) g_dinv[i] = rsqrtf((float)g_deg[i]);
}

// ---------------------------------------------------------------------------
// GEMM: out = dinv[row] * (A[row,:] @ W)   (K = 128 fixed)
// MODE 1: A = x (ext), writes g_h1 and g_agg1 (NCOL=128)
// MODE 2: A = g_h1,    writes g_h2 and outExt (NCOL=64)
// Tile: 64 rows x NCOL cols, 256 threads, each thread 4 rows x CPT cols.
// ---------------------------------------------------------------------------
template <int NCOL, int CPT, int MODE>
__launch_bounds__(256)
__global__ void k_gemm(const float* __restrict__ Aext,
                       const float* __restrict__ Wg,
                       float* __restrict__ outExt, int n) {
    constexpr int TR = 64;
    constexpr int XP = 68;  // padded row length for transposed x tile (16B-aligned, conflict-free)
    extern __shared__ float sm[];
    float* sW = sm;                 // [128 * NCOL]
    float* sX = sm + 128 * NCOL;    // [128][XP]  (xT[k][r])

    const float* A = (MODE == 1) ? Aext : g_h1;
    const int tid  = threadIdx.x;
    const int row0 = blockIdx.x * TR;

    // Load W (L2-resident across blocks)
    const float4* W4 = (const float4*)Wg;
    float4* sW4 = (float4*)sW;
    #pragma unroll
    for (int i = tid; i < 128 * NCOL / 4; i += 256) sW4[i] = W4[i];

    // Load A tile transposed. Lanes consecutive in r -> conflict-free STS.
    for (int i = tid; i < TR * 32; i += 256) {
        int r  = i & 63;
        int k4 = i >> 6;
        int gr = row0 + r;
        float4 v = make_float4(0.f, 0.f, 0.f, 0.f);
        if (gr < n) v = ((const float4*)A)[(size_t)gr * 32 + k4];
        sX[(k4 * 4 + 0) * XP + r] = v.x;
        sX[(k4 * 4 + 1) * XP + r] = v.y;
        sX[(k4 * 4 + 2) * XP + r] = v.z;
        sX[(k4 * 4 + 3) * XP + r] = v.w;
    }
    __syncthreads();

    constexpr int CG = NCOL / CPT;          // 16
    const int cg = tid % CG;
    const int rg = tid / CG;                // 0..15
    const int c0 = cg * CPT;
    const int r0 = rg * 4;

    float acc[4][CPT];
    #pragma unroll
    for (int r = 0; r < 4; r++)
        #pragma unroll
        for (int c = 0; c < CPT; c++) acc[r][c] = 0.f;

    #pragma unroll 4
    for (int k = 0; k < 128; k++) {
        float4 xa = *(const float4*)&sX[k * XP + r0];
        float xr[4] = {xa.x, xa.y, xa.z, xa.w};
        float wc[CPT];
        #pragma unroll
        for (int c = 0; c < CPT; c += 4) {
            float4 w = *(const float4*)&sW[k * NCOL + c0 + c];
            wc[c] = w.x; wc[c + 1] = w.y; wc[c + 2] = w.z; wc[c + 3] = w.w;
        }
        #pragma unroll
        for (int r = 0; r < 4; r++)
            #pragma unroll
            for (int c = 0; c < CPT; c++)
                acc[r][c] = fmaf(xr[r], wc[c], acc[r][c]);
    }

    #pragma unroll
    for (int r = 0; r < 4; r++) {
        int gr = row0 + r0 + r;
        if (gr >= n) continue;
        float dv = g_dinv[gr];
        #pragma unroll
        for (int c = 0; c < CPT; c += 4) {
            float4 o = make_float4(acc[r][c] * dv, acc[r][c + 1] * dv,
                                   acc[r][c + 2] * dv, acc[r][c + 3] * dv);
            size_t off = (size_t)gr * NCOL + c0 + c;
            if (MODE == 1) {
                *(float4*)&g_h1[off]   = o;
                *(float4*)&g_agg1[off] = o;   // aggregation init = self-loop term
            } else {
                *(float4*)&g_h2[off]   = o;
                *(float4*)&outExt[off] = o;   // d_out init = self-loop term
            }
        }
    }
}

// ---------------------------------------------------------------------------
// Edge scatter-add with vectorized L2 reductions
// ---------------------------------------------------------------------------
__device__ __forceinline__ void red_add_v4(float4* p, float4 v) {
    asm volatile("red.global.add.v4.f32 [%0], {%1, %2, %3, %4};"
                 :: "l"(p), "f"(v.x), "f"(v.y), "f"(v.z), "f"(v.w) : "memory");
}

// conv1: 128 floats/edge -> 1 warp per edge, lane handles one float4 chunk
__global__ void k_scatter1(const int* __restrict__ ei, int E) {
    int lane = threadIdx.x & 31;
    int gw   = (blockIdx.x * blockDim.x + threadIdx.x) >> 5;
    int nw   = (gridDim.x * blockDim.x) >> 5;
    for (int e = gw; e < E; e += nw) {
        int s = __ldg(&ei[e]);
        int d = __ldg(&ei[E + e]);
        float4 v = ((const float4*)(g_h1 + (size_t)s * 128))[lane];
        red_add_v4(((float4*)(g_agg1 + (size_t)d * 128)) + lane, v);
    }
}

// conv2: 64 floats/edge -> half-warp per edge
__global__ void k_scatter2(const int* __restrict__ ei, float* __restrict__ out, int E) {
    int t  = blockIdx.x * blockDim.x + threadIdx.x;
    int ch = t & 15;
    int gh = t >> 4;
    int nh = (gridDim.x * blockDim.x) >> 4;
    for (int e = gh; e < E; e += nh) {
        int s = __ldg(&ei[e]);
        int d = __ldg(&ei[E + e]);
        float4 v = ((const float4*)(g_h2 + (size_t)s * 64))[ch];
        red_add_v4(((float4*)(out + (size_t)d * 64)) + ch, v);
    }
}

// ---------------------------------------------------------------------------
// Elementwise epilogues
// ---------------------------------------------------------------------------
// a1 = relu(dinv[row] * agg1 + b1)  -> stored into g_h1 (reuse)
__global__ void k_relu(const float* __restrict__ b1, int n) {
    int i = blockIdx.x * blockDim.x + threadIdx.x;  // float4 index
    if (i >= n * 32) return;
    int row = i >> 5;
    int c4  = i & 31;
    float dv = g_dinv[row];
    float4 v = ((const float4*)g_agg1)[i];
    float4 b = __ldg(&((const float4*)b1)[c4]);
    float4 o;
    o.x = fmaxf(fmaf(v.x, dv, b.x), 0.f);
    o.y = fmaxf(fmaf(v.y, dv, b.y), 0.f);
    o.z = fmaxf(fmaf(v.z, dv, b.z), 0.f);
    o.w = fmaxf(fmaf(v.w, dv, b.w), 0.f);
    ((float4*)g_h1)[i] = o;
}

// out = dinv[row] * out + b2  (in place)
__global__ void k_out(float* __restrict__ out, const float* __restrict__ b2, int n) {
    int i = blockIdx.x * blockDim.x + threadIdx.x;  // float4 index
    if (i >= n * 16) return;
    int row = i >> 4;
    int c4  = i & 15;
    float dv = g_dinv[row];
    float4 v = ((float4*)out)[i];
    float4 b = __ldg(&((const float4*)b2)[c4]);
    v.x = fmaf(v.x, dv, b.x);
    v.y = fmaf(v.y, dv, b.y);
    v.z = fmaf(v.z, dv, b.z);
    v.w = fmaf(v.w, dv, b.w);
    ((float4*)out)[i] = v;
}

// ---------------------------------------------------------------------------
// Launch
// ---------------------------------------------------------------------------
extern "C" void kernel_launch(void* const* d_in, const int* in_sizes, int n_in,
                              void* d_out, int out_size) {
    const float* x  = (const float*)d_in[0];
    const int*   ei = (const int*)  d_in[1];
    const float* W1 = (const float*)d_in[2];
    const float* b1 = (const float*)d_in[3];
    const float* W2 = (const float*)d_in[4];
    const float* b2 = (const float*)d_in[5];
    float* out = (float*)d_out;

    const int n = in_sizes[0] / 128;
    const int E = in_sizes[1] / 2;

    const int smem1 = (128 * 128 + 128 * 68) * sizeof(float);  // 100352
    const int smem2 = (128 * 64  + 128 * 68) * sizeof(float);  // 67584
    cudaFuncSetAttribute(k_gemm<128, 8, 1>, cudaFuncAttributeMaxDynamicSharedMemorySize, smem1);
    cudaFuncSetAttribute(k_gemm<64,  4, 2>, cudaFuncAttributeMaxDynamicSharedMemorySize, smem2);

    // 1) degrees + dinv
    k_deg_init<<<(n + 255) / 256, 256>>>(n);
    k_deg_count<<<(E + 255) / 256, 256>>>(ei, E);
    k_dinv<<<(n + 255) / 256, 256>>>(n);

    // 2) conv1 transform (+ self-loop init of agg1)
    k_gemm<128, 8, 1><<<(n + 63) / 64, 256, smem1>>>(x, W1, nullptr, n);

    // 3) conv1 edge aggregation
    k_scatter1<<<1480, 256>>>(ei, E);

    // 4) relu(dinv*agg1 + b1) -> g_h1
    k_relu<<<(n * 32 + 255) / 256, 256>>>(b1, n);

    // 5) conv2 transform (+ self-loop init of d_out)
    k_gemm<64, 4, 2><<<(n + 63) / 64, 256, smem2>>>(nullptr, W2, out, n);

    // 6) conv2 edge aggregation into d_out
    k_scatter2<<<1480, 256>>>(ei, out, E);

    // 7) out = dinv*out + b2
    k_out<<<(n * 16 + 255) / 256, 256>>>(out, b2, n);
}

// round 2
// speedup vs baseline: 1.6160x; 1.6160x over previous
#include <cuda_runtime.h>
#include <cstdint>

#define NMAX 100000
#define EMAX 1600000
#define SCAN_BLK 1024

// Scratch (device globals: allocation-free rule)
__device__ int   g_deg [NMAX];                 // in-degree (no self loop)
__device__ int   g_off [NMAX];                 // CSR row starts (exclusive scan of deg)
__device__ int   g_cur [NMAX];                 // fill cursors
__device__ int   g_part[256];                  // scan block partials
__device__ int   g_csr [EMAX];                 // src indices grouped by dst
__device__ float g_dinv[NMAX];
__device__ float g_h1 [(size_t)NMAX * 128];    // dinv-scaled conv1 transform
__device__ float g_a1 [(size_t)NMAX * 128];    // relu(conv1) activations
__device__ float g_h2 [(size_t)NMAX * 64];     // dinv-scaled conv2 transform

// ---------------------------------------------------------------------------
// Degree histogram + exclusive scan + CSR fill
// ---------------------------------------------------------------------------
__global__ void k_zero_deg(int n) {
    int i = blockIdx.x * blockDim.x + threadIdx.x;
    if (i < n) g_deg[i] = 0;
}

__global__ void k_deg(const int* __restrict__ ei, int E) {
    int i = blockIdx.x * blockDim.x + threadIdx.x;
    if (i < E) atomicAdd(&g_deg[ei[E + i]], 1);
}

// exclusive scan, 1024 elements per block
__global__ void k_scan1(int n) {
    __shared__ int sw[32];
    int tid = threadIdx.x;
    int i = blockIdx.x * SCAN_BLK + tid;
    int v = (i < n) ? g_deg[i] : 0;
    int x = v;
    #pragma unroll
    for (int o = 1; o < 32; o <<= 1) {
        int y = __shfl_up_sync(0xffffffffu, x, o);
        if ((tid & 31) >= o) x += y;
    }
    if ((tid & 31) == 31) sw[tid >> 5] = x;
    __syncthreads();
    if (tid < 32) {
        int y = sw[tid];
        #pragma unroll
        for (int o = 1; o < 32; o <<= 1) {
            int z = __shfl_up_sync(0xffffffffu, y, o);
            if (tid >= o) y += z;
        }
        sw[tid] = y;
    }
    __syncthreads();
    int wp = (tid >= 32) ? sw[(tid >> 5) - 1] : 0;
    if (i < n) g_off[i] = wp + x - v;             // exclusive within block
    if (tid == SCAN_BLK - 1) g_part[blockIdx.x] = wp + x;  // block total
}

// scan the <=128 block totals (exclusive, in place)
__global__ void k_scan2(int nb) {
    __shared__ int sw[4];
    int t = threadIdx.x;  // 128 threads
    int v = (t < nb) ? g_part[t] : 0;
    int x = v;
    #pragma unroll
    for (int o = 1; o < 32; o <<= 1) {
        int y = __shfl_up_sync(0xffffffffu, x, o);
        if ((t & 31) >= o) x += y;
    }
    if ((t & 31) == 31) sw[t >> 5] = x;
    __syncthreads();
    if (t == 0) {
        int run = 0;
        #pragma unroll
        for (int j = 0; j < 4; j++) { int tmp = sw[j]; sw[j] = run; run += tmp; }
    }
    __syncthreads();
    int wp = sw[t >> 5];
    if (t < nb) g_part[t] = wp + x - v;
}

// finalize offsets, cursors, dinv (deg+1 accounts for the self loop)
__global__ void k_finish(int n) {
    int i = blockIdx.x * blockDim.x + threadIdx.x;
    if (i >= n) return;
    int off = g_off[i] + g_part[i >> 10];
    g_off[i] = off;
    g_cur[i] = off;
    g_dinv[i] = rsqrtf((float)(g_deg[i] + 1));
}

__global__ void k_fill(const int* __restrict__ ei, int E) {
    int e = blockIdx.x * blockDim.x + threadIdx.x;
    if (e >= E) return;
    int s = ei[e];
    int d = ei[E + e];
    int p = atomicAdd(&g_cur[d], 1);
    g_csr[p] = s;
}

// ---------------------------------------------------------------------------
// GEMM: out = dinv[row] * (A @ W).  128-row tile, 256 threads, 8x8 / 8x4 per
// thread. MODE 1: A=x -> g_h1 (NCOL=128). MODE 2: A=g_a1 -> g_h2 (NCOL=64).
// ---------------------------------------------------------------------------
template <int NCOL, int CPT, int MODE>
__launch_bounds__(256, 1)
__global__ void k_gemm(const float* __restrict__ Aext,
                       const float* __restrict__ Wg, int n) {
    constexpr int TR = 128;
    extern __shared__ float sm[];
    float* sW = sm;               // [128][NCOL]
    float* sX = sm + 128 * NCOL;  // [128][128]  transposed A tile (xT[k][r])

    const float* A = (MODE == 1) ? Aext : g_a1;
    float* Od      = (MODE == 1) ? g_h1 : g_h2;
    const int tid  = threadIdx.x;
    const int row0 = blockIdx.x * TR;

    const float4* W4 = (const float4*)Wg;
    float4* sW4 = (float4*)sW;
    #pragma unroll
    for (int i = tid; i < 128 * NCOL / 4; i += 256) sW4[i] = W4[i];

    for (int i = tid; i < TR * 32; i += 256) {
        int r  = i & 127;
        int k4 = i >> 7;
        int gr = row0 + r;
        float4 v = make_float4(0.f, 0.f, 0.f, 0.f);
        if (gr < n) v = ((const float4*)A)[(size_t)gr * 32 + k4];
        sX[(k4 * 4 + 0) * 128 + r] = v.x;
        sX[(k4 * 4 + 1) * 128 + r] = v.y;
        sX[(k4 * 4 + 2) * 128 + r] = v.z;
        sX[(k4 * 4 + 3) * 128 + r] = v.w;
    }
    __syncthreads();

    const int c0 = (tid & 15) * CPT;
    const int r0 = (tid >> 4) * 8;

    float acc[8][CPT];
    #pragma unroll
    for (int r = 0; r < 8; r++)
        #pragma unroll
        for (int c = 0; c < CPT; c++) acc[r][c] = 0.f;

    #pragma unroll 2
    for (int k = 0; k < 128; k++) {
        float xr[8];
        *(float4*)&xr[0] = *(const float4*)&sX[k * 128 + r0];
        *(float4*)&xr[4] = *(const float4*)&sX[k * 128 + r0 + 4];
        float wc[CPT];
        #pragma unroll
        for (int c = 0; c < CPT; c += 4)
            *(float4*)&wc[c] = *(const float4*)&sW[k * NCOL + c0 + c];
        #pragma unroll
        for (int r = 0; r < 8; r++)
            #pragma unroll
            for (int c = 0; c < CPT; c++)
                acc[r][c] = fmaf(xr[r], wc[c], acc[r][c]);
    }

    #pragma unroll
    for (int r = 0; r < 8; r++) {
        int gr = row0 + r0 + r;
        if (gr >= n) continue;
        float dv = g_dinv[gr];
        #pragma unroll
        for (int c = 0; c < CPT; c += 4) {
            float4 o = make_float4(acc[r][c] * dv, acc[r][c + 1] * dv,
                                   acc[r][c + 2] * dv, acc[r][c + 3] * dv);
            *(float4*)&Od[(size_t)gr * NCOL + c0 + c] = o;
        }
    }
}

// ---------------------------------------------------------------------------
// Gather aggregation (CSR, no atomics), fused epilogues
// ---------------------------------------------------------------------------
// conv1: warp per node, lane owns one float4 of 128 floats.
// g_a1[d] = relu(dinv[d] * (g_h1[d] + sum_{s->d} g_h1[s]) + b1)
__global__ void k_gather1(const float* __restrict__ b1, int n) {
    int t = blockIdx.x * blockDim.x + threadIdx.x;
    int lane = t & 31;
    int w = t >> 5;
    if (w >= n) return;
    int st = g_off[w], cnt = g_deg[w];
    const float4* H = (const float4*)g_h1;
    float4 acc = H[(size_t)w * 32 + lane];  // self loop
    int j = 0;
    for (; j + 4 <= cnt; j += 4) {
        int s0 = g_csr[st + j], s1 = g_csr[st + j + 1];
        int s2 = g_csr[st + j + 2], s3 = g_csr[st + j + 3];
        float4 v0 = H[(size_t)s0 * 32 + lane];
        float4 v1 = H[(size_t)s1 * 32 + lane];
        float4 v2 = H[(size_t)s2 * 32 + lane];
        float4 v3 = H[(size_t)s3 * 32 + lane];
        acc.x += (v0.x + v1.x) + (v2.x + v3.x);
        acc.y += (v0.y + v1.y) + (v2.y + v3.y);
        acc.z += (v0.z + v1.z) + (v2.z + v3.z);
        acc.w += (v0.w + v1.w) + (v2.w + v3.w);
    }
    for (; j < cnt; j++) {
        int s = g_csr[st + j];
        float4 v = H[(size_t)s * 32 + lane];
        acc.x += v.x; acc.y += v.y; acc.z += v.z; acc.w += v.w;
    }
    float dv = g_dinv[w];
    float4 b = ((const float4*)b1)[lane];
    float4 o;
    o.x = fmaxf(fmaf(acc.x, dv, b.x), 0.f);
    o.y = fmaxf(fmaf(acc.y, dv, b.y), 0.f);
    o.z = fmaxf(fmaf(acc.z, dv, b.z), 0.f);
    o.w = fmaxf(fmaf(acc.w, dv, b.w), 0.f);
    ((float4*)g_a1)[(size_t)w * 32 + lane] = o;
}

// conv2: 16-lane group per node, lane owns one float4 of 64 floats.
// out[d] = dinv[d] * (g_h2[d] + sum_{s->d} g_h2[s]) + b2
__global__ void k_gather2(float* __restrict__ out, const float* __restrict__ b2, int n) {
    int t = blockIdx.x * blockDim.x + threadIdx.x;
    int ch = t & 15;
    int g = t >> 4;
    if (g >= n) return;
    int st = g_off[g], cnt = g_deg[g];
    const float4* H = (const float4*)g_h2;
    float4 acc = H[(size_t)g * 16 + ch];  // self loop
    int j = 0;
    for (; j + 4 <= cnt; j += 4) {
        int s0 = g_csr[st + j], s1 = g_csr[st + j + 1];
        int s2 = g_csr[st + j + 2], s3 = g_csr[st + j + 3];
        float4 v0 = H[(size_t)s0 * 16 + ch];
        float4 v1 = H[(size_t)s1 * 16 + ch];
        float4 v2 = H[(size_t)s2 * 16 + ch];
        float4 v3 = H[(size_t)s3 * 16 + ch];
        acc.x += (v0.x + v1.x) + (v2.x + v3.x);
        acc.y += (v0.y + v1.y) + (v2.y + v3.y);
        acc.z += (v0.z + v1.z) + (v2.z + v3.z);
        acc.w += (v0.w + v1.w) + (v2.w + v3.w);
    }
    for (; j < cnt; j++) {
        int s = g_csr[st + j];
        float4 v = H[(size_t)s * 16 + ch];
        acc.x += v.x; acc.y += v.y; acc.z += v.z; acc.w += v.w;
    }
    float dv = g_dinv[g];
    float4 b = ((const float4*)b2)[ch];
    acc.x = fmaf(acc.x, dv, b.x);
    acc.y = fmaf(acc.y, dv, b.y);
    acc.z = fmaf(acc.z, dv, b.z);
    acc.w = fmaf(acc.w, dv, b.w);
    ((float4*)out)[(size_t)g * 16 + ch] = acc;
}

// ---------------------------------------------------------------------------
// Launch
// ---------------------------------------------------------------------------
extern "C" void kernel_launch(void* const* d_in, const int* in_sizes, int n_in,
                              void* d_out, int out_size) {
    const float* x  = (const float*)d_in[0];
    const int*   ei = (const int*)  d_in[1];
    const float* W1 = (const float*)d_in[2];
    const float* b1 = (const float*)d_in[3];
    const float* W2 = (const float*)d_in[4];
    const float* b2 = (const float*)d_in[5];
    float* out = (float*)d_out;

    const int n = in_sizes[0] / 128;
    const int E = in_sizes[1] / 2;
    const int nb = (n + SCAN_BLK - 1) / SCAN_BLK;

    const int smem1 = (128 * 128 + 128 * 128) * sizeof(float);  // 131072
    const int smem2 = (128 * 64  + 128 * 128) * sizeof(float);  // 98304
    cudaFuncSetAttribute(k_gemm<128, 8, 1>, cudaFuncAttributeMaxDynamicSharedMemorySize, smem1);
    cudaFuncSetAttribute(k_gemm<64,  4, 2>, cudaFuncAttributeMaxDynamicSharedMemorySize, smem2);

    // CSR build + normalization
    k_zero_deg<<<(n + 255) / 256, 256>>>(n);
    k_deg<<<(E + 255) / 256, 256>>>(ei, E);
    k_scan1<<<nb, SCAN_BLK>>>(n);
    k_scan2<<<1, 128>>>(nb);
    k_finish<<<(n + 255) / 256, 256>>>(n);
    k_fill<<<(E + 255) / 256, 256>>>(ei, E);

    // conv1
    k_gemm<128, 8, 1><<<(n + 127) / 128, 256, smem1>>>(x, W1, n);
    k_gather1<<<(n * 32 + 255) / 256, 256>>>(b1, n);

    // conv2
    k_gemm<64, 4, 2><<<(n + 127) / 128, 256, smem2>>>(nullptr, W2, n);
    k_gather2<<<(n * 16 + 255) / 256, 256>>>(out, b2, n);
}

// round 7
// speedup vs baseline: 2.4058x; 1.4887x over previous
#include <cuda_runtime.h>
#include <cuda_bf16.h>
#include <cstdint>

#define NMAX 100000
#define EMAX 1600000
#define SCAN_BLK 1024

// ---------------------------------------------------------------------------
// Device scratch (allocation-free rule)
// ---------------------------------------------------------------------------
__device__ int   g_deg [NMAX];
__device__ int   g_off [NMAX];
__device__ int   g_cur [NMAX];
__device__ int   g_part[256];
__device__ int   g_csr [EMAX];
__device__ float g_dinv[NMAX];
__device__ float g_h1 [(size_t)NMAX * 128];
__device__ float g_a1 [(size_t)NMAX * 128];
__device__ float g_h2 [(size_t)NMAX * 64];
// bf16 weight blobs (hi/lo split), dense [n][k] rows of 256B
__device__ __align__(16) uint32_t g_w1hi[8192], g_w1lo[8192];  // 128 x 64 u32
__device__ __align__(16) uint32_t g_w2hi[4096], g_w2lo[4096];  // 64  x 64 u32

// ---------------------------------------------------------------------------
// PTX helpers (portable sm_80+ path)
// ---------------------------------------------------------------------------
__device__ __forceinline__ void mma_bf16(float* c, const uint32_t* a, const uint32_t* b) {
    asm volatile("mma.sync.aligned.m16n8k16.row.col.f32.bf16.bf16.f32 "
                 "{%0,%1,%2,%3}, {%4,%5,%6,%7}, {%8,%9}, {%0,%1,%2,%3};"
                 : "+f"(c[0]), "+f"(c[1]), "+f"(c[2]), "+f"(c[3])
                 : "r"(a[0]), "r"(a[1]), "r"(a[2]), "r"(a[3]), "r"(b[0]), "r"(b[1]));
}
__device__ __forceinline__ uint32_t pack_bf16(float a, float b) {
    __nv_bfloat162 h = __floats2bfloat162_rn(a, b);
    return *(uint32_t*)&h;
}

// ---------------------------------------------------------------------------
// CSR build (degree histogram + scan + fill) — proven in R2
// ---------------------------------------------------------------------------
__global__ void k_zero_deg(int n) {
    int i = blockIdx.x * blockDim.x + threadIdx.x;
    if (i < n) g_deg[i] = 0;
}
__global__ void k_deg(const int* __restrict__ ei, int E) {
    int i = blockIdx.x * blockDim.x + threadIdx.x;
    if (i < E) atomicAdd(&g_deg[ei[E + i]], 1);
}
__global__ void k_scan1(int n) {
    __shared__ int sw[32];
    int tid = threadIdx.x;
    int i = blockIdx.x * SCAN_BLK + tid;
    int v = (i < n) ? g_deg[i] : 0;
    int x = v;
    #pragma unroll
    for (int o = 1; o < 32; o <<= 1) {
        int y = __shfl_up_sync(0xffffffffu, x, o);
        if ((tid & 31) >= o) x += y;
    }
    if ((tid & 31) == 31) sw[tid >> 5] = x;
    __syncthreads();
    if (tid < 32) {
        int y = sw[tid];
        #pragma unroll
        for (int o = 1; o < 32; o <<= 1) {
            int z = __shfl_up_sync(0xffffffffu, y, o);
            if (tid >= o) y += z;
        }
        sw[tid] = y;
    }
    __syncthreads();
    int wp = (tid >= 32) ? sw[(tid >> 5) - 1] : 0;
    if (i < n) g_off[i] = wp + x - v;
    if (tid == SCAN_BLK - 1) g_part[blockIdx.x] = wp + x;
}
__global__ void k_scan2(int nb) {
    __shared__ int sw[4];
    int t = threadIdx.x;
    int v = (t < nb) ? g_part[t] : 0;
    int x = v;
    #pragma unroll
    for (int o = 1; o < 32; o <<= 1) {
        int y = __shfl_up_sync(0xffffffffu, x, o);
        if ((t & 31) >= o) x += y;
    }
    if ((t & 31) == 31) sw[t >> 5] = x;
    __syncthreads();
    if (t == 0) {
        int run = 0;
        #pragma unroll
        for (int j = 0; j < 4; j++) { int tmp = sw[j]; sw[j] = run; run += tmp; }
    }
    __syncthreads();
    int wp = sw[t >> 5];
    if (t < nb) g_part[t] = wp + x - v;
}
__global__ void k_finish(int n) {
    int i = blockIdx.x * blockDim.x + threadIdx.x;
    if (i >= n) return;
    int off = g_off[i] + g_part[i >> 10];
    g_off[i] = off;
    g_cur[i] = off;
    g_dinv[i] = rsqrtf((float)(g_deg[i] + 1));
}
__global__ void k_fill(const int* __restrict__ ei, int E) {
    int e = blockIdx.x * blockDim.x + threadIdx.x;
    if (e >= E) return;
    int s = ei[e];
    int d = ei[E + e];
    int p = atomicAdd(&g_cur[d], 1);
    g_csr[p] = s;
}

// ---------------------------------------------------------------------------
// Weight prep: fp32 W [128 x Nc] -> bf16 hi/lo blobs, dense [n][k] (256B rows)
// FIX (R7): destination globals selected INSIDE device code. Passing __device__
// symbols as host-side kernel args (R4-R6) writes through the host shadow
// address -> illegal address -> poisoned context -> rel_err 1.0.
// ---------------------------------------------------------------------------
template <int Nc, int MODE>
__global__ void k_wprep(const float* __restrict__ W) {
    uint32_t* bhi = (MODE == 1) ? g_w1hi : g_w2hi;
    uint32_t* blo = (MODE == 1) ? g_w1lo : g_w2lo;
    int i = blockIdx.x * blockDim.x + threadIdx.x;   // (n, k-pair)
    if (i >= Nc * 64) return;
    int nn = i >> 6;
    int k2 = i & 63;
    int k = k2 << 1;
    float v0 = W[k * Nc + nn];
    float v1 = W[(k + 1) * Nc + nn];
    __nv_bfloat16 h0 = __float2bfloat16(v0);
    __nv_bfloat16 h1 = __float2bfloat16(v1);
    uint32_t hi = (uint32_t)(*(uint16_t*)&h0) | ((uint32_t)(*(uint16_t*)&h1) << 16);
    uint32_t lo = pack_bf16(v0 - __bfloat162float(h0), v1 - __bfloat162float(h1));
    bhi[nn * 64 + k2] = hi;
    blo[nn * 64 + k2] = lo;
}

// ---------------------------------------------------------------------------
// Tensor-core GEMM via mma.sync bf16x3: Od = dinv[row] * (A @ W)
// 64-row CTA tile, padded SMEM (row stride 272B), direct u32 fragment loads.
// conv1: warp grid 2m x 4n (32x32/warp, MF=2, NF=4), smem 104448
// conv2: warp grid 4m x 2n (16x32/warp, MF=1, NF=4), smem  69632
// ---------------------------------------------------------------------------
template <int NCOL, int MODE>
__launch_bounds__(256, 1)
__global__ void k_tc_gemm(const float* __restrict__ Aext, int n) {
    constexpr int TR  = 64;
    constexpr int NWM = (NCOL == 128) ? 2 : 4;
    constexpr int MF  = TR / (NWM * 16);
    constexpr int NWN = 8 / NWM;
    constexpr int NF  = NCOL / (NWN * 8);
    constexpr int STR = 272;                 // padded row stride (bytes)
    constexpr int A_HI = 0;
    constexpr int A_LO = TR * STR;
    constexpr int B_HI = 2 * TR * STR;
    constexpr int B_LO = B_HI + NCOL * STR;

    extern __shared__ char smraw[];
    char* sm = smraw;

    const int tid  = threadIdx.x;
    const int wid  = tid >> 5;
    const int lane = tid & 31;
    const int row0 = blockIdx.x * TR;

    const float* A = (MODE == 1) ? Aext : g_a1;
    float* Od      = (MODE == 1) ? g_h1 : g_h2;
    const uint32_t* Bhig = (MODE == 1) ? g_w1hi : g_w2hi;
    const uint32_t* Blog = (MODE == 1) ? g_w1lo : g_w2lo;

    // Stage weights: dense 256B rows -> padded 272B rows
    {
        const uint4* bh4 = (const uint4*)Bhig;
        const uint4* bl4 = (const uint4*)Blog;
        constexpr int NB4 = NCOL * 16;
        #pragma unroll
        for (int i = tid; i < NB4; i += 256) {
            int r  = i >> 4;
            int kc = i & 15;
            *(uint4*)(sm + B_HI + r * STR + kc * 16) = bh4[i];
            *(uint4*)(sm + B_LO + r * STR + kc * 16) = bl4[i];
        }
    }

    // Load + split-convert A tile (64 x 128 fp32 -> bf16 hi/lo)
    #pragma unroll
    for (int i = tid; i < TR * 16; i += 256) {   // (r, 16B chunk)
        int r  = i >> 4;
        int kc = i & 15;
        int gr = row0 + r;
        float4 va = make_float4(0.f, 0.f, 0.f, 0.f);
        float4 vb = make_float4(0.f, 0.f, 0.f, 0.f);
        if (gr < n) {
            va = ((const float4*)A)[(size_t)gr * 32 + kc * 2];
            vb = ((const float4*)A)[(size_t)gr * 32 + kc * 2 + 1];
        }
        __nv_bfloat162 h01 = __floats2bfloat162_rn(va.x, va.y);
        __nv_bfloat162 h23 = __floats2bfloat162_rn(va.z, va.w);
        __nv_bfloat162 h45 = __floats2bfloat162_rn(vb.x, vb.y);
        __nv_bfloat162 h67 = __floats2bfloat162_rn(vb.z, vb.w);
        uint4 hi = make_uint4(*(uint32_t*)&h01, *(uint32_t*)&h23,
                              *(uint32_t*)&h45, *(uint32_t*)&h67);
        uint4 lo;
        lo.x = pack_bf16(va.x - __bfloat162float(h01.x), va.y - __bfloat162float(h01.y));
        lo.y = pack_bf16(va.z - __bfloat162float(h23.x), va.w - __bfloat162float(h23.y));
        lo.z = pack_bf16(vb.x - __bfloat162float(h45.x), vb.y - __bfloat162float(h45.y));
        lo.w = pack_bf16(vb.z - __bfloat162float(h67.x), vb.w - __bfloat162float(h67.y));
        *(uint4*)(sm + A_HI + r * STR + kc * 16) = hi;
        *(uint4*)(sm + A_LO + r * STR + kc * 16) = lo;
    }
    __syncthreads();

    const int wm   = wid % NWM;
    const int wn   = wid / NWM;
    const int mrow = wm * (MF * 16);
    const int ncol = wn * (NF * 8);
    const int gr4  = lane >> 2;        // 0..7
    const int cl2  = (lane & 3) * 2;   // 0,2,4,6 (bf16 element index)

    float acc[MF][NF][4];
    #pragma unroll
    for (int mf = 0; mf < MF; mf++)
        #pragma unroll
        for (int nf = 0; nf < NF; nf++)
            #pragma unroll
            for (int j = 0; j < 4; j++) acc[mf][nf][j] = 0.f;

    #pragma unroll
    for (int ks = 0; ks < 8; ks++) {
        const int kb = (ks * 16 + cl2) * 2;          // byte offset of k pair
        uint32_t ahi[MF][4], alo[MF][4];
        #pragma unroll
        for (int mf = 0; mf < MF; mf++) {
            int ro = (mrow + mf * 16 + gr4) * STR + kb;
            ahi[mf][0] = *(const uint32_t*)(sm + A_HI + ro);
            ahi[mf][1] = *(const uint32_t*)(sm + A_HI + ro + 8 * STR);
            ahi[mf][2] = *(const uint32_t*)(sm + A_HI + ro + 16);
            ahi[mf][3] = *(const uint32_t*)(sm + A_HI + ro + 8 * STR + 16);
            alo[mf][0] = *(const uint32_t*)(sm + A_LO + ro);
            alo[mf][1] = *(const uint32_t*)(sm + A_LO + ro + 8 * STR);
            alo[mf][2] = *(const uint32_t*)(sm + A_LO + ro + 16);
            alo[mf][3] = *(const uint32_t*)(sm + A_LO + ro + 8 * STR + 16);
        }
        uint32_t bhi[NF][2], blo[NF][2];
        #pragma unroll
        for (int nf = 0; nf < NF; nf++) {
            int ro = (ncol + nf * 8 + gr4) * STR + kb;
            bhi[nf][0] = *(const uint32_t*)(sm + B_HI + ro);
            bhi[nf][1] = *(const uint32_t*)(sm + B_HI + ro + 16);
            blo[nf][0] = *(const uint32_t*)(sm + B_LO + ro);
            blo[nf][1] = *(const uint32_t*)(sm + B_LO + ro + 16);
        }
        #pragma unroll
        for (int mf = 0; mf < MF; mf++)
            #pragma unroll
            for (int nf = 0; nf < NF; nf++) {
                mma_bf16(acc[mf][nf], ahi[mf], bhi[nf]);
                mma_bf16(acc[mf][nf], ahi[mf], blo[nf]);
                mma_bf16(acc[mf][nf], alo[mf], bhi[nf]);
            }
    }

    // Epilogue: scale by dinv, store float2 per fragment half
    #pragma unroll
    for (int mf = 0; mf < MF; mf++) {
        int r0g = row0 + mrow + mf * 16 + gr4;
        int r1g = r0g + 8;
        float dv0 = (r0g < n) ? g_dinv[r0g] : 0.f;
        float dv1 = (r1g < n) ? g_dinv[r1g] : 0.f;
        #pragma unroll
        for (int nf = 0; nf < NF; nf++) {
            int c = ncol + nf * 8 + cl2;
            if (r0g < n) {
                float2 o = make_float2(acc[mf][nf][0] * dv0, acc[mf][nf][1] * dv0);
                *(float2*)&Od[(size_t)r0g * NCOL + c] = o;
            }
            if (r1g < n) {
                float2 o = make_float2(acc[mf][nf][2] * dv1, acc[mf][nf][3] * dv1);
                *(float2*)&Od[(size_t)r1g * NCOL + c] = o;
            }
        }
    }
}

// ---------------------------------------------------------------------------
// Gather aggregation (CSR, no atomics), fused epilogues — proven in R2
// ---------------------------------------------------------------------------
__global__ void k_gather1(const float* __restrict__ b1, int n) {
    int t = blockIdx.x * blockDim.x + threadIdx.x;
    int lane = t & 31;
    int w = t >> 5;
    if (w >= n) return;
    int st = g_off[w], cnt = g_deg[w];
    const float4* H = (const float4*)g_h1;
    float4 acc = H[(size_t)w * 32 + lane];
    int j = 0;
    for (; j + 4 <= cnt; j += 4) {
        int s0 = g_csr[st + j], s1 = g_csr[st + j + 1];
        int s2 = g_csr[st + j + 2], s3 = g_csr[st + j + 3];
        float4 v0 = H[(size_t)s0 * 32 + lane];
        float4 v1 = H[(size_t)s1 * 32 + lane];
        float4 v2 = H[(size_t)s2 * 32 + lane];
        float4 v3 = H[(size_t)s3 * 32 + lane];
        acc.x += (v0.x + v1.x) + (v2.x + v3.x);
        acc.y += (v0.y + v1.y) + (v2.y + v3.y);
        acc.z += (v0.z + v1.z) + (v2.z + v3.z);
        acc.w += (v0.w + v1.w) + (v2.w + v3.w);
    }
    for (; j < cnt; j++) {
        int s = g_csr[st + j];
        float4 v = H[(size_t)s * 32 + lane];
        acc.x += v.x; acc.y += v.y; acc.z += v.z; acc.w += v.w;
    }
    float dv = g_dinv[w];
    float4 b = ((const float4*)b1)[lane];
    float4 o;
    o.x = fmaxf(fmaf(acc.x, dv, b.x), 0.f);
    o.y = fmaxf(fmaf(acc.y, dv, b.y), 0.f);
    o.z = fmaxf(fmaf(acc.z, dv, b.z), 0.f);
    o.w = fmaxf(fmaf(acc.w, dv, b.w), 0.f);
    ((float4*)g_a1)[(size_t)w * 32 + lane] = o;
}

__global__ void k_gather2(float* __restrict__ out, const float* __restrict__ b2, int n) {
    int t = blockIdx.x * blockDim.x + threadIdx.x;
    int ch = t & 15;
    int g = t >> 4;
    if (g >= n) return;
    int st = g_off[g], cnt = g_deg[g];
    const float4* H = (const float4*)g_h2;
    float4 acc = H[(size_t)g * 16 + ch];
    int j = 0;
    for (; j + 4 <= cnt; j += 4) {
        int s0 = g_csr[st + j], s1 = g_csr[st + j + 1];
        int s2 = g_csr[st + j + 2], s3 = g_csr[st + j + 3];
        float4 v0 = H[(size_t)s0 * 16 + ch];
        float4 v1 = H[(size_t)s1 * 16 + ch];
        float4 v2 = H[(size_t)s2 * 16 + ch];
        float4 v3 = H[(size_t)s3 * 16 + ch];
        acc.x += (v0.x + v1.x) + (v2.x + v3.x);
        acc.y += (v0.y + v1.y) + (v2.y + v3.y);
        acc.z += (v0.z + v1.z) + (v2.z + v3.z);
        acc.w += (v0.w + v1.w) + (v2.w + v3.w);
    }
    for (; j < cnt; j++) {
        int s = g_csr[st + j];
        float4 v = H[(size_t)s * 16 + ch];
        acc.x += v.x; acc.y += v.y; acc.z += v.z; acc.w += v.w;
    }
    float dv = g_dinv[g];
    float4 b = ((const float4*)b2)[ch];
    acc.x = fmaf(acc.x, dv, b.x);
    acc.y = fmaf(acc.y, dv, b.y);
    acc.z = fmaf(acc.z, dv, b.z);
    acc.w = fmaf(acc.w, dv, b.w);
    ((float4*)out)[(size_t)g * 16 + ch] = acc;
}

// ---------------------------------------------------------------------------
// Launch
// ---------------------------------------------------------------------------
extern "C" void kernel_launch(void* const* d_in, const int* in_sizes, int n_in,
                              void* d_out, int out_size) {
    const float* x  = (const float*)d_in[0];
    const int*   ei = (const int*)  d_in[1];
    const float* W1 = (const float*)d_in[2];
    const float* b1 = (const float*)d_in[3];
    const float* W2 = (const float*)d_in[4];
    const float* b2 = (const float*)d_in[5];
    float* out = (float*)d_out;

    const int n = in_sizes[0] / 128;
    const int E = in_sizes[1] / 2;
    const int nb = (n + SCAN_BLK - 1) / SCAN_BLK;

    const int smem1 = 2 * 64 * 272 + 2 * 128 * 272;  // 104448
    const int smem2 = 2 * 64 * 272 + 2 * 64  * 272;  //  69632
    cudaFuncSetAttribute(k_tc_gemm<128, 1>, cudaFuncAttributeMaxDynamicSharedMemorySize, smem1);
    cudaFuncSetAttribute(k_tc_gemm<64,  2>, cudaFuncAttributeMaxDynamicSharedMemorySize, smem2);

    // Weight prep (bf16 hi/lo, dense layout; globals bound in device code)
    k_wprep<128, 1><<<32, 256>>>(W1);
    k_wprep<64,  2><<<16, 256>>>(W2);

    // CSR build + normalization
    k_zero_deg<<<(n + 255) / 256, 256>>>(n);
    k_deg<<<(E + 255) / 256, 256>>>(ei, E);
    k_scan1<<<nb, SCAN_BLK>>>(n);
    k_scan2<<<1, 128>>>(nb);
    k_finish<<<(n + 255) / 256, 256>>>(n);
    k_fill<<<(E + 255) / 256, 256>>>(ei, E);

    const int gg = (n + 63) / 64;

    // conv1
    k_tc_gemm<128, 1><<<gg, 256, smem1>>>(x, n);
    k_gather1<<<(n * 32 + 255) / 256, 256>>>(b1, n);

    // conv2
    k_tc_gemm<64, 2><<<gg, 256, smem2>>>(nullptr, n);
    k_gather2<<<(n * 16 + 255) / 256, 256>>>(out, b2, n);
}

// round 8
// speedup vs baseline: 2.7726x; 1.1525x over previous
#include <cuda_runtime.h>
#include <cuda_bf16.h>
#include <cuda_fp16.h>
#include <cstdint>

#define NMAX 100000
#define EMAX 1600000
#define SCAN_BLK 1024

// ---------------------------------------------------------------------------
// Device scratch (allocation-free rule)
// ---------------------------------------------------------------------------
__device__ int    g_deg [NMAX];
__device__ int    g_off [NMAX];
__device__ int    g_cur [NMAX];
__device__ int    g_part[256];
__device__ int    g_csr [EMAX];
__device__ float  g_dinv[NMAX];
__device__ __align__(16) __half g_h1 [(size_t)NMAX * 128];  // fp16 intermediates
__device__ __align__(16) __half g_a1 [(size_t)NMAX * 128];
__device__ __align__(16) __half g_h2 [(size_t)NMAX * 64];
// bf16 weight blobs (hi/lo split), dense [n][k] rows of 256B
__device__ __align__(16) uint32_t g_w1hi[8192], g_w1lo[8192];
__device__ __align__(16) uint32_t g_w2hi[4096], g_w2lo[4096];

// ---------------------------------------------------------------------------
// Helpers
// ---------------------------------------------------------------------------
__device__ __forceinline__ void mma_bf16(float* c, const uint32_t* a, const uint32_t* b) {
    asm volatile("mma.sync.aligned.m16n8k16.row.col.f32.bf16.bf16.f32 "
                 "{%0,%1,%2,%3}, {%4,%5,%6,%7}, {%8,%9}, {%0,%1,%2,%3};"
                 : "+f"(c[0]), "+f"(c[1]), "+f"(c[2]), "+f"(c[3])
                 : "r"(a[0]), "r"(a[1]), "r"(a[2]), "r"(a[3]), "r"(b[0]), "r"(b[1]));
}
__device__ __forceinline__ uint32_t pack_bf16(float a, float b) {
    __nv_bfloat162 h = __floats2bfloat162_rn(a, b);
    return *(uint32_t*)&h;
}
__device__ __forceinline__ uint32_t f2_to_h2(float x, float y) {
    __half2 h = __floats2half2_rn(x, y);
    return *(uint32_t*)&h;
}
__device__ __forceinline__ float4 h4_to_f4(uint2 v) {
    float2 fa = __half22float2(*(__half2*)&v.x);
    float2 fb = __half22float2(*(__half2*)&v.y);
    return make_float4(fa.x, fa.y, fb.x, fb.y);
}

// ---------------------------------------------------------------------------
// CSR build (degree histogram + scan + fill) — proven
// ---------------------------------------------------------------------------
__global__ void k_zero_deg(int n) {
    int i = blockIdx.x * blockDim.x + threadIdx.x;
    if (i < n) g_deg[i] = 0;
}
__global__ void k_deg(const int* __restrict__ ei, int E) {
    int i = blockIdx.x * blockDim.x + threadIdx.x;
    if (i < E) atomicAdd(&g_deg[ei[E + i]], 1);
}
__global__ void k_scan1(int n) {
    __shared__ int sw[32];
    int tid = threadIdx.x;
    int i = blockIdx.x * SCAN_BLK + tid;
    int v = (i < n) ? g_deg[i] : 0;
    int x = v;
    #pragma unroll
    for (int o = 1; o < 32; o <<= 1) {
        int y = __shfl_up_sync(0xffffffffu, x, o);
        if ((tid & 31) >= o) x += y;
    }
    if ((tid & 31) == 31) sw[tid >> 5] = x;
    __syncthreads();
    if (tid < 32) {
        int y = sw[tid];
        #pragma unroll
        for (int o = 1; o < 32; o <<= 1) {
            int z = __shfl_up_sync(0xffffffffu, y, o);
            if (tid >= o) y += z;
        }
        sw[tid] = y;
    }
    __syncthreads();
    int wp = (tid >= 32) ? sw[(tid >> 5) - 1] : 0;
    if (i < n) g_off[i] = wp + x - v;
    if (tid == SCAN_BLK - 1) g_part[blockIdx.x] = wp + x;
}
__global__ void k_scan2(int nb) {
    __shared__ int sw[4];
    int t = threadIdx.x;
    int v = (t < nb) ? g_part[t] : 0;
    int x = v;
    #pragma unroll
    for (int o = 1; o < 32; o <<= 1) {
        int y = __shfl_up_sync(0xffffffffu, x, o);
        if ((t & 31) >= o) x += y;
    }
    if ((t & 31) == 31) sw[t >> 5] = x;
    __syncthreads();
    if (t == 0) {
        int run = 0;
        #pragma unroll
        for (int j = 0; j < 4; j++) { int tmp = sw[j]; sw[j] = run; run += tmp; }
    }
    __syncthreads();
    int wp = sw[t >> 5];
    if (t < nb) g_part[t] = wp + x - v;
}
__global__ void k_finish(int n) {
    int i = blockIdx.x * blockDim.x + threadIdx.x;
    if (i >= n) return;
    int off = g_off[i] + g_part[i >> 10];
    g_off[i] = off;
    g_cur[i] = off;
    g_dinv[i] = rsqrtf((float)(g_deg[i] + 1));
}
__global__ void k_fill(const int* __restrict__ ei, int E) {
    int e = blockIdx.x * blockDim.x + threadIdx.x;
    if (e >= E) return;
    int s = ei[e];
    int d = ei[E + e];
    int p = atomicAdd(&g_cur[d], 1);
    g_csr[p] = s;
}

// ---------------------------------------------------------------------------
// Weight prep (globals bound in device code — R7 fix)
// ---------------------------------------------------------------------------
template <int Nc, int MODE>
__global__ void k_wprep(const float* __restrict__ W) {
    uint32_t* bhi = (MODE == 1) ? g_w1hi : g_w2hi;
    uint32_t* blo = (MODE == 1) ? g_w1lo : g_w2lo;
    int i = blockIdx.x * blockDim.x + threadIdx.x;
    if (i >= Nc * 64) return;
    int nn = i >> 6;
    int k2 = i & 63;
    int k = k2 << 1;
    float v0 = W[k * Nc + nn];
    float v1 = W[(k + 1) * Nc + nn];
    __nv_bfloat16 h0 = __float2bfloat16(v0);
    __nv_bfloat16 h1 = __float2bfloat16(v1);
    uint32_t hi = (uint32_t)(*(uint16_t*)&h0) | ((uint32_t)(*(uint16_t*)&h1) << 16);
    uint32_t lo = pack_bf16(v0 - __bfloat162float(h0), v1 - __bfloat162float(h1));
    bhi[nn * 64 + k2] = hi;
    blo[nn * 64 + k2] = lo;
}

// ---------------------------------------------------------------------------
// Tensor-core GEMM via mma.sync bf16x3: Od(fp16) = dinv[row] * (A @ W)
// MODE 1: A = x (fp32 ext) -> g_h1.  MODE 2: A = g_a1 (fp16) -> g_h2.
// 64-row CTA tile, padded SMEM (row stride 272B), direct u32 fragment loads.
// ---------------------------------------------------------------------------
template <int NCOL, int MODE>
__launch_bounds__(256, 1)
__global__ void k_tc_gemm(const float* __restrict__ Aext, int n) {
    constexpr int TR  = 64;
    constexpr int NWM = (NCOL == 128) ? 2 : 4;
    constexpr int MF  = TR / (NWM * 16);
    constexpr int NWN = 8 / NWM;
    constexpr int NF  = NCOL / (NWN * 8);
    constexpr int STR = 272;
    constexpr int A_HI = 0;
    constexpr int A_LO = TR * STR;
    constexpr int B_HI = 2 * TR * STR;
    constexpr int B_LO = B_HI + NCOL * STR;

    extern __shared__ char smraw[];
    char* sm = smraw;

    const int tid  = threadIdx.x;
    const int wid  = tid >> 5;
    const int lane = tid & 31;
    const int row0 = blockIdx.x * TR;

    __half* Od = (MODE == 1) ? g_h1 : g_h2;
    const uint32_t* Bhig = (MODE == 1) ? g_w1hi : g_w2hi;
    const uint32_t* Blog = (MODE == 1) ? g_w1lo : g_w2lo;

    // Stage weights: dense 256B rows -> padded 272B rows
    {
        const uint4* bh4 = (const uint4*)Bhig;
        const uint4* bl4 = (const uint4*)Blog;
        constexpr int NB4 = NCOL * 16;
        #pragma unroll
        for (int i = tid; i < NB4; i += 256) {
            int r  = i >> 4;
            int kc = i & 15;
            *(uint4*)(sm + B_HI + r * STR + kc * 16) = bh4[i];
            *(uint4*)(sm + B_LO + r * STR + kc * 16) = bl4[i];
        }
    }

    // Load + split-convert A tile (64 x 128 -> bf16 hi/lo)
    #pragma unroll
    for (int i = tid; i < TR * 16; i += 256) {   // (r, 8-elem k-chunk)
        int r  = i >> 4;
        int kc = i & 15;
        int gr = row0 + r;
        float f[8];
        if (MODE == 1) {
            float4 va = make_float4(0.f, 0.f, 0.f, 0.f);
            float4 vb = make_float4(0.f, 0.f, 0.f, 0.f);
            if (gr < n) {
                va = ((const float4*)Aext)[(size_t)gr * 32 + kc * 2];
                vb = ((const float4*)Aext)[(size_t)gr * 32 + kc * 2 + 1];
            }
            f[0] = va.x; f[1] = va.y; f[2] = va.z; f[3] = va.w;
            f[4] = vb.x; f[5] = vb.y; f[6] = vb.z; f[7] = vb.w;
        } else {
            uint4 v = make_uint4(0u, 0u, 0u, 0u);
            if (gr < n) v = ((const uint4*)g_a1)[(size_t)gr * 16 + kc];
            float2 f0 = __half22float2(*(__half2*)&v.x);
            float2 f1 = __half22float2(*(__half2*)&v.y);
            float2 f2 = __half22float2(*(__half2*)&v.z);
            float2 f3 = __half22float2(*(__half2*)&v.w);
            f[0] = f0.x; f[1] = f0.y; f[2] = f1.x; f[3] = f1.y;
            f[4] = f2.x; f[5] = f2.y; f[6] = f3.x; f[7] = f3.y;
        }
        uint4 hi, lo;
        uint32_t* hp = (uint32_t*)&hi;
        uint32_t* lp = (uint32_t*)&lo;
        #pragma unroll
        for (int j = 0; j < 4; j++) {
            __nv_bfloat162 h = __floats2bfloat162_rn(f[2 * j], f[2 * j + 1]);
            hp[j] = *(uint32_t*)&h;
            lp[j] = pack_bf16(f[2 * j]     - __bfloat162float(h.x),
                              f[2 * j + 1] - __bfloat162float(h.y));
        }
        *(uint4*)(sm + A_HI + r * STR + kc * 16) = hi;
        *(uint4*)(sm + A_LO + r * STR + kc * 16) = lo;
    }
    __syncthreads();

    const int wm   = wid % NWM;
    const int wn   = wid / NWM;
    const int mrow = wm * (MF * 16);
    const int ncol = wn * (NF * 8);
    const int gr4  = lane >> 2;
    const int cl2  = (lane & 3) * 2;

    float acc[MF][NF][4];
    #pragma unroll
    for (int mf = 0; mf < MF; mf++)
        #pragma unroll
        for (int nf = 0; nf < NF; nf++)
            #pragma unroll
            for (int j = 0; j < 4; j++) acc[mf][nf][j] = 0.f;

    #pragma unroll
    for (int ks = 0; ks < 8; ks++) {
        const int kb = (ks * 16 + cl2) * 2;
        uint32_t ahi[MF][4], alo[MF][4];
        #pragma unroll
        for (int mf = 0; mf < MF; mf++) {
            int ro = (mrow + mf * 16 + gr4) * STR + kb;
            ahi[mf][0] = *(const uint32_t*)(sm + A_HI + ro);
            ahi[mf][1] = *(const uint32_t*)(sm + A_HI + ro + 8 * STR);
            ahi[mf][2] = *(const uint32_t*)(sm + A_HI + ro + 16);
            ahi[mf][3] = *(const uint32_t*)(sm + A_HI + ro + 8 * STR + 16);
            alo[mf][0] = *(const uint32_t*)(sm + A_LO + ro);
            alo[mf][1] = *(const uint32_t*)(sm + A_LO + ro + 8 * STR);
            alo[mf][2] = *(const uint32_t*)(sm + A_LO + ro + 16);
            alo[mf][3] = *(const uint32_t*)(sm + A_LO + ro + 8 * STR + 16);
        }
        uint32_t bhi[NF][2], blo[NF][2];
        #pragma unroll
        for (int nf = 0; nf < NF; nf++) {
            int ro = (ncol + nf * 8 + gr4) * STR + kb;
            bhi[nf][0] = *(const uint32_t*)(sm + B_HI + ro);
            bhi[nf][1] = *(const uint32_t*)(sm + B_HI + ro + 16);
            blo[nf][0] = *(const uint32_t*)(sm + B_LO + ro);
            blo[nf][1] = *(const uint32_t*)(sm + B_LO + ro + 16);
        }
        #pragma unroll
        for (int mf = 0; mf < MF; mf++)
            #pragma unroll
            for (int nf = 0; nf < NF; nf++) {
                mma_bf16(acc[mf][nf], ahi[mf], bhi[nf]);
                mma_bf16(acc[mf][nf], ahi[mf], blo[nf]);
                mma_bf16(acc[mf][nf], alo[mf], bhi[nf]);
            }
    }

    // Epilogue: scale by dinv, store half2 per fragment half
    #pragma unroll
    for (int mf = 0; mf < MF; mf++) {
        int r0g = row0 + mrow + mf * 16 + gr4;
        int r1g = r0g + 8;
        float dv0 = (r0g < n) ? g_dinv[r0g] : 0.f;
        float dv1 = (r1g < n) ? g_dinv[r1g] : 0.f;
        #pragma unroll
        for (int nf = 0; nf < NF; nf++) {
            int c = ncol + nf * 8 + cl2;
            if (r0g < n) {
                uint32_t p = f2_to_h2(acc[mf][nf][0] * dv0, acc[mf][nf][1] * dv0);
                *(uint32_t*)&Od[(size_t)r0g * NCOL + c] = p;
            }
            if (r1g < n) {
                uint32_t p = f2_to_h2(acc[mf][nf][2] * dv1, acc[mf][nf][3] * dv1);
                *(uint32_t*)&Od[(size_t)r1g * NCOL + c] = p;
            }
        }
    }
}

// ---------------------------------------------------------------------------
// Gather aggregation (CSR, no atomics), fp16 reads, fp32 accumulate
// ---------------------------------------------------------------------------
// conv1: warp per node, lane owns 4 cols (8B) of the 128-col fp16 row.
// g_a1[d] = fp16(relu(dinv[d]*(h1[d] + sum h1[s]) + b1))
__global__ void k_gather1(const float* __restrict__ b1, int n) {
    int t = blockIdx.x * blockDim.x + threadIdx.x;
    int lane = t & 31;
    int w = t >> 5;
    if (w >= n) return;
    int st = g_off[w], cnt = g_deg[w];
    const uint2* H = (const uint2*)g_h1;       // 32 chunks of 8B per row
    float4 acc = h4_to_f4(H[(size_t)w * 32 + lane]);
    int j = 0;
    for (; j + 4 <= cnt; j += 4) {
        int s0 = g_csr[st + j], s1 = g_csr[st + j + 1];
        int s2 = g_csr[st + j + 2], s3 = g_csr[st + j + 3];
        float4 v0 = h4_to_f4(H[(size_t)s0 * 32 + lane]);
        float4 v1 = h4_to_f4(H[(size_t)s1 * 32 + lane]);
        float4 v2 = h4_to_f4(H[(size_t)s2 * 32 + lane]);
        float4 v3 = h4_to_f4(H[(size_t)s3 * 32 + lane]);
        acc.x += (v0.x + v1.x) + (v2.x + v3.x);
        acc.y += (v0.y + v1.y) + (v2.y + v3.y);
        acc.z += (v0.z + v1.z) + (v2.z + v3.z);
        acc.w += (v0.w + v1.w) + (v2.w + v3.w);
    }
    for (; j < cnt; j++) {
        int s = g_csr[st + j];
        float4 v = h4_to_f4(H[(size_t)s * 32 + lane]);
        acc.x += v.x; acc.y += v.y; acc.z += v.z; acc.w += v.w;
    }
    float dv = g_dinv[w];
    float4 b = ((const float4*)b1)[lane];
    float ox = fmaxf(fmaf(acc.x, dv, b.x), 0.f);
    float oy = fmaxf(fmaf(acc.y, dv, b.y), 0.f);
    float oz = fmaxf(fmaf(acc.z, dv, b.z), 0.f);
    float ow = fmaxf(fmaf(acc.w, dv, b.w), 0.f);
    uint2 o;
    o.x = f2_to_h2(ox, oy);
    o.y = f2_to_h2(oz, ow);
    ((uint2*)g_a1)[(size_t)w * 32 + lane] = o;
}

// conv2: 16-lane group per node, lane owns 4 cols (8B) of the 64-col fp16 row.
// out(fp32) = dinv[d]*(h2[d] + sum h2[s]) + b2
__global__ void k_gather2(float* __restrict__ out, const float* __restrict__ b2, int n) {
    int t = blockIdx.x * blockDim.x + threadIdx.x;
    int ch = t & 15;
    int g = t >> 4;
    if (g >= n) return;
    int st = g_off[g], cnt = g_deg[g];
    const uint2* H = (const uint2*)g_h2;       // 16 chunks of 8B per row
    float4 acc = h4_to_f4(H[(size_t)g * 16 + ch]);
    int j = 0;
    for (; j + 4 <= cnt; j += 4) {
        int s0 = g_csr[st + j], s1 = g_csr[st + j + 1];
        int s2 = g_csr[st + j + 2], s3 = g_csr[st + j + 3];
        float4 v0 = h4_to_f4(H[(size_t)s0 * 16 + ch]);
        float4 v1 = h4_to_f4(H[(size_t)s1 * 16 + ch]);
        float4 v2 = h4_to_f4(H[(size_t)s2 * 16 + ch]);
        float4 v3 = h4_to_f4(H[(size_t)s3 * 16 + ch]);
        acc.x += (v0.x + v1.x) + (v2.x + v3.x);
        acc.y += (v0.y + v1.y) + (v2.y + v3.y);
        acc.z += (v0.z + v1.z) + (v2.z + v3.z);
        acc.w += (v0.w + v1.w) + (v2.w + v3.w);
    }
    for (; j < cnt; j++) {
        int s = g_csr[st + j];
        float4 v = h4_to_f4(H[(size_t)s * 16 + ch]);
        acc.x += v.x; acc.y += v.y; acc.z += v.z; acc.w += v.w;
    }
    float dv = g_dinv[g];
    float4 b = ((const float4*)b2)[ch];
    acc.x = fmaf(acc.x, dv, b.x);
    acc.y = fmaf(acc.y, dv, b.y);
    acc.z = fmaf(acc.z, dv, b.z);
    acc.w = fmaf(acc.w, dv, b.w);
    ((float4*)out)[(size_t)g * 16 + ch] = acc;
}

// ---------------------------------------------------------------------------
// Launch
// ---------------------------------------------------------------------------
extern "C" void kernel_launch(void* const* d_in, const int* in_sizes, int n_in,
                              void* d_out, int out_size) {
    const float* x  = (const float*)d_in[0];
    const int*   ei = (const int*)  d_in[1];
    const float* W1 = (const float*)d_in[2];
    const float* b1 = (const float*)d_in[3];
    const float* W2 = (const float*)d_in[4];
    const float* b2 = (const float*)d_in[5];
    float* out = (float*)d_out;

    const int n = in_sizes[0] / 128;
    const int E = in_sizes[1] / 2;
    const int nb = (n + SCAN_BLK - 1) / SCAN_BLK;

    const int smem1 = 2 * 64 * 272 + 2 * 128 * 272;  // 104448
    const int smem2 = 2 * 64 * 272 + 2 * 64  * 272;  //  69632
    cudaFuncSetAttribute(k_tc_gemm<128, 1>, cudaFuncAttributeMaxDynamicSharedMemorySize, smem1);
    cudaFuncSetAttribute(k_tc_gemm<64,  2>, cudaFuncAttributeMaxDynamicSharedMemorySize, smem2);

    // Weight prep
    k_wprep<128, 1><<<32, 256>>>(W1);
    k_wprep<64,  2><<<16, 256>>>(W2);

    // CSR build + normalization
    k_zero_deg<<<(n + 255) / 256, 256>>>(n);
    k_deg<<<(E + 255) / 256, 256>>>(ei, E);
    k_scan1<<<nb, SCAN_BLK>>>(n);
    k_scan2<<<1, 128>>>(nb);
    k_finish<<<(n + 255) / 256, 256>>>(n);
    k_fill<<<(E + 255) / 256, 256>>>(ei, E);

    const int gg = (n + 63) / 64;

    // conv1
    k_tc_gemm<128, 1><<<gg, 256, smem1>>>(x, n);
    k_gather1<<<(n * 32 + 255) / 256, 256>>>(b1, n);

    // conv2
    k_tc_gemm<64, 2><<<gg, 256, smem2>>>(nullptr, n);
    k_gather2<<<(n * 16 + 255) / 256, 256>>>(out, b2, n);
}